// round 16
// baseline (speedup 1.0000x reference)
#include <cuda_runtime.h>

#define B_ROWS 2048
#define BN_EPS 1e-5f

typedef unsigned long long ull;
typedef long long ll;

// GMEM scratch: transposed operands (coalesced column access for both layers)
__device__ float g_xT[64 * 2048];                 // 512 KB, L2-resident
__device__ float g_t0T[65536ULL * 2048];          // 512 MB, normalized t0 transposed

__device__ __forceinline__ ull pack2(float lo, float hi) {
    ull r; asm("mov.b64 %0, {%1, %2};" : "=l"(r) : "f"(lo), "f"(hi)); return r;
}
__device__ __forceinline__ void unpack2(ull v, float& lo, float& hi) {
    asm("mov.b64 {%0, %1}, %2;" : "=f"(lo), "=f"(hi) : "l"(v));
}
__device__ __forceinline__ ull fma2(ull a, ull b, ull c) {
    ull d; asm("fma.rn.f32x2 %0, %1, %2, %3;" : "=l"(d) : "l"(a), "l"(b), "l"(c)); return d;
}
// accurate tanh (~1e-7 rel): MUFU.TANH at ~5e-4 is too close to the 1e-3 gate
__device__ __forceinline__ float ftanh(float x) {
    float e = __expf(2.0f * x);
    return 1.0f - __fdividef(2.0f, e + 1.0f);
}

// ============================ transpose x -> xT [64][2048] ============================
__global__ void xT_kernel(const float* __restrict__ x)
{
    __shared__ float t[32][33];
    int bx = blockIdx.x;          // d-tile (0..1)
    int by = blockIdx.y;          // row-tile (0..63)
    int lx = threadIdx.x, ly = threadIdx.y;   // 32 x 8
    #pragma unroll
    for (int k = 0; k < 4; ++k)
        t[ly + k * 8][lx] = x[(ll)(by * 32 + ly + k * 8) * 64 + bx * 32 + lx];
    __syncthreads();
    #pragma unroll
    for (int k = 0; k < 4; ++k)
        g_xT[(ll)(bx * 32 + ly + k * 8) * 2048 + by * 32 + lx] = t[lx][ly + k * 8];
}

// ============================ L0 kernel ============================
// 1024 threads (32 warps/SM), block = 2 terms, RPT=2 rows/thread. Direct
// coalesced LDG.32 mainloop from xT with register double-buffer prefetch;
// ZERO mainloop barriers -> extra warps convert directly into latency cover.
// tanh packed IN PLACE into acc so the 64-reg cap at 1024 threads holds.
#define T0 1024
#define NW0 (T0 / 32)        // 32 warps
#define RPT0 (B_ROWS / T0)   // 2

__device__ __forceinline__ void l0_fetch(float (&buf)[4][RPT0], int c, int tid) {
    #pragma unroll
    for (int d = 0; d < 4; ++d)
        #pragma unroll
        for (int r = 0; r < RPT0; ++r)
            buf[d][r] = g_xT[(ll)(c * 4 + d) * 2048 + tid + r * T0];
}

__device__ __forceinline__ void l0_compute(const float (&buf)[4][RPT0], int c,
                                           const ulonglong2* __restrict__ shw2,
                                           ull (&acc)[RPT0][8]) {
    #pragma unroll
    for (int d = 0; d < 4; ++d) {
        int k = c * 4 + d;
        #pragma unroll
        for (int g = 0; g < 2; ++g) {
            ulonglong2 w01 = shw2[(g * 64 + k) * 2];
            ulonglong2 w23 = shw2[(g * 64 + k) * 2 + 1];
            #pragma unroll
            for (int r = 0; r < RPT0; ++r) {
                ull xx = pack2(buf[d][r], buf[d][r]);
                acc[r][g * 4 + 0] = fma2(xx, w01.x, acc[r][g * 4 + 0]);
                acc[r][g * 4 + 1] = fma2(xx, w01.y, acc[r][g * 4 + 1]);
                acc[r][g * 4 + 2] = fma2(xx, w23.x, acc[r][g * 4 + 2]);
                acc[r][g * 4 + 3] = fma2(xx, w23.y, acc[r][g * 4 + 3]);
            }
        }
    }
}

__global__ void __launch_bounds__(T0, 1)
l0_kernel(int mofs,
          const float* __restrict__ Wp,  const float* __restrict__ bp,
          const float* __restrict__ gp,  const float* __restrict__ bep,
          const float* __restrict__ Wap, const float* __restrict__ bap,
          const float* __restrict__ gap, const float* __restrict__ beap,
          float* __restrict__ out_t, float* __restrict__ out_a, int M)
{
    constexpr int F  = 16;
    constexpr int FA = 4;

    extern __shared__ float sm[];
    float* tile   = sm;                      // [16][2048] octet-rotated store tile
    float* sh_w   = sm + 16 * B_ROWS;        // [1024]
    float* red    = sh_w + 1024;             // [F*NW0*2] = 1024
    float* stA    = red + F * NW0 * 2;       // [16]
    float* stB    = stA + F;
    float* saA    = stB + F;                 // [4]
    float* saB    = saA + FA;
    float* sb0    = saB + FA;                // [16]
    float* sg0    = sb0 + F;
    float* sbe0   = sg0 + F;
    float* swa    = sbe0 + F;                // [32]
    float* sba    = swa + 32;                // [4]
    float* sga    = sba + FA;
    float* sbea   = sga + FA;

    const int tid  = threadIdx.x;
    const int lane = tid & 31;
    const int warp = tid >> 5;
    const int m0   = (blockIdx.x + mofs) * 2;

    // ---- params to smem ----
    if (tid < 1024) sh_w[tid] = Wp[(ll)m0 * 512 + tid];
    if (tid < F) {
        sb0[tid]  = bp[m0 * 8 + tid];
        sg0[tid]  = gp[m0 * 8 + tid];
        sbe0[tid] = bep[m0 * 8 + tid];
    }
    if (tid < 32) swa[tid] = Wap[m0 * 16 + tid];
    if (tid < FA) {
        sba[tid]  = bap[m0 * 2 + tid];
        sga[tid]  = gap[m0 * 2 + tid];
        sbea[tid] = beap[m0 * 2 + tid];
    }
    __syncthreads();

    // ---- Phase 1: GEMM (64 -> 16), double-buffered register prefetch ----
    ull acc[RPT0][8];
    #pragma unroll
    for (int r = 0; r < RPT0; ++r)
        #pragma unroll
        for (int j = 0; j < 8; ++j) acc[r][j] = 0ull;

    const ulonglong2* shw2 = reinterpret_cast<const ulonglong2*>(sh_w);

    float xA[4][RPT0], xB[4][RPT0];
    l0_fetch(xA, 0, tid);                    // preload chunk 0

    #pragma unroll 1
    for (int cc = 0; cc < 8; ++cc) {
        int c0 = 2 * cc, c1 = 2 * cc + 1;
        l0_fetch(xB, c1, tid);               // prefetch c1 while computing c0
        l0_compute(xA, c0, shw2, acc);
        if (cc < 7) l0_fetch(xA, c1 + 1, tid);
        l0_compute(xB, c1, shw2, acc);
    }

    // ---- Phase 2: bias + tanh IN PLACE (feats P = (j>>2)*8 + (j&3)*2) ----
    #pragma unroll
    for (int r = 0; r < RPT0; ++r)
        #pragma unroll
        for (int j = 0; j < 8; ++j) {
            int P = (j >> 2) * 8 + (j & 3) * 2;
            float lo, hi; unpack2(acc[r][j], lo, hi);
            acc[r][j] = pack2(ftanh(lo + sb0[P]), ftanh(hi + sb0[P + 1]));
        }

    // ---- batch stats per packed pair ----
    #pragma unroll
    for (int j = 0; j < 8; ++j) {
        float s0 = 0.f, q0 = 0.f, s1 = 0.f, q1 = 0.f;
        #pragma unroll
        for (int r = 0; r < RPT0; ++r) {
            float lo, hi; unpack2(acc[r][j], lo, hi);
            s0 += lo; q0 += lo * lo;
            s1 += hi; q1 += hi * hi;
        }
        #pragma unroll
        for (int o = 16; o; o >>= 1) {
            s0 += __shfl_xor_sync(0xffffffffu, s0, o);
            q0 += __shfl_xor_sync(0xffffffffu, q0, o);
            s1 += __shfl_xor_sync(0xffffffffu, s1, o);
            q1 += __shfl_xor_sync(0xffffffffu, q1, o);
        }
        if (lane == 0) {
            int P = (j >> 2) * 8 + (j & 3) * 2;
            red[P * NW0 + warp]           = s0;
            red[(F + P) * NW0 + warp]     = q0;
            red[(P + 1) * NW0 + warp]     = s1;
            red[(F + P + 1) * NW0 + warp] = q1;
        }
    }
    __syncthreads();
    if (tid < F) {
        int f = tid;
        float s = 0.f, ss = 0.f;
        #pragma unroll
        for (int w = 0; w < NW0; ++w) { s += red[f * NW0 + w]; ss += red[(F + f) * NW0 + w]; }
        float mu  = s  * (1.f / B_ROWS);
        float var = ss * (1.f / B_ROWS) - mu * mu;
        float a   = sg0[f] * rsqrtf(var + BN_EPS);
        stA[f] = a;
        stB[f] = sbe0[f] - mu * a;
    }
    __syncthreads();

    // ---- Phase 3: normalize -> t0T (coalesced STG.32) + tile -> out_t; aux fused ----
    float av[RPT0][FA];
    #pragma unroll
    for (int q = 0; q < RPT0; ++q) {
        int row = tid + q * T0;
        int rb32 = row & ~31;
        float tn[F];
        #pragma unroll
        for (int j = 0; j < 8; ++j) {
            int P = (j >> 2) * 8 + (j & 3) * 2;
            float lo, hi; unpack2(acc[q][j], lo, hi);
            tn[P]     = fmaf(stA[P],     lo, stB[P]);
            tn[P + 1] = fmaf(stA[P + 1], hi, stB[P + 1]);
        }

        // transposed scratch for L1: lanes = consecutive rows -> coalesced
        #pragma unroll
        for (int f = 0; f < F; ++f)
            g_t0T[(ll)(m0 * 8 + f) * 2048 + row] = tn[f];

        // octet-rotated tile for the output-layout store
        #pragma unroll
        for (int f = 0; f < F; ++f)
            tile[f * B_ROWS + rb32 + ((row + 8 * (f >> 2)) & 31)] = tn[f];

        #pragma unroll
        for (int g = 0; g < 2; ++g)
            #pragma unroll
            for (int k = 0; k < 2; ++k) {
                float a = sba[g * 2 + k];
                #pragma unroll
                for (int h = 0; h < 8; ++h)
                    a = fmaf(tn[g * 8 + h], swa[(g * 8 + h) * 2 + k], a);
                av[q][g * 2 + k] = ftanh(a);
            }
    }
    __syncthreads();

    // cooperative output-layout store: 2048 rows x 4 parts = 8192 items (8 iters)
    #pragma unroll
    for (int ii = 0; ii < 8; ++ii) {
        int j   = tid + ii * T0;
        int row = j >> 2;
        int p   = j & 3;
        int rb  = (row & ~31) + ((row + 8 * p) & 31);
        float4 v;
        v.x = tile[(p * 4 + 0) * B_ROWS + rb];
        v.y = tile[(p * 4 + 1) * B_ROWS + rb];
        v.z = tile[(p * 4 + 2) * B_ROWS + rb];
        v.w = tile[(p * 4 + 3) * B_ROWS + rb];
        *reinterpret_cast<float4*>(&out_t[(ll)row * M * 8 + m0 * 8 + p * 4]) = v;
    }

    // ---- Phase 4: aux stats + store ----
    #pragma unroll
    for (int f = 0; f < FA; ++f) {
        float s = 0.f, ss = 0.f;
        #pragma unroll
        for (int r = 0; r < RPT0; ++r) { float v = av[r][f]; s += v; ss += v * v; }
        #pragma unroll
        for (int o = 16; o; o >>= 1) {
            s  += __shfl_xor_sync(0xffffffffu, s, o);
            ss += __shfl_xor_sync(0xffffffffu, ss, o);
        }
        if (lane == 0) { red[f * NW0 + warp] = s; red[(FA + f) * NW0 + warp] = ss; }
    }
    __syncthreads();
    if (tid < FA) {
        int f = tid;
        float s = 0.f, ss = 0.f;
        #pragma unroll
        for (int w = 0; w < NW0; ++w) { s += red[f * NW0 + w]; ss += red[(FA + f) * NW0 + w]; }
        float mu  = s  * (1.f / B_ROWS);
        float var = ss * (1.f / B_ROWS) - mu * mu;
        float a   = sga[f] * rsqrtf(var + BN_EPS);
        saA[f] = a;
        saB[f] = sbea[f] - mu * a;
    }
    __syncthreads();

    #pragma unroll
    for (int r = 0; r < RPT0; ++r) {
        int b = tid + r * T0;
        ll obase = ((ll)b * M + m0) * 2;
        float4 v;
        v.x = fmaf(saA[0], av[r][0], saB[0]);
        v.y = fmaf(saA[1], av[r][1], saB[1]);
        v.z = fmaf(saA[2], av[r][2], saB[2]);
        v.w = fmaf(saA[3], av[r][3], saB[3]);
        *reinterpret_cast<float4*>(&out_a[obase]) = v;
    }
}

// ============================ L1 kernel (R14 verbatim — ~135us) ============================
#define T1 512
#define NW1 (T1 / 32)
#define RPT1 (B_ROWS / T1)   // 4

__global__ void __launch_bounds__(T1, 1)
l1_kernel(const float* __restrict__ Wp,  const float* __restrict__ bp,
          const float* __restrict__ gp,  const float* __restrict__ bep,
          const float* __restrict__ Wap, const float* __restrict__ bap,
          const float* __restrict__ gap, const float* __restrict__ beap,
          float* __restrict__ out_t, float* __restrict__ out_a, int M)
{
    constexpr int F = 8, FA = 2;

    __shared__ float sh_w[512];
    __shared__ float sb0[F], sg0[F], sbe0[F];
    __shared__ float swa[16];
    __shared__ float sba[FA], sga[FA], sbea[FA];
    __shared__ float red[F * NW1 * 2];
    __shared__ float stA[F], stB[F];
    __shared__ float saA[FA], saB[FA];

    const int tid  = threadIdx.x;
    const int lane = tid & 31;
    const int warp = tid >> 5;
    const int m0   = blockIdx.x;

    for (int i = tid; i < 512; i += T1) sh_w[i] = Wp[(ll)m0 * 512 + i];
    if (tid < F) {
        sb0[tid]  = bp[m0 * 8 + tid];
        sg0[tid]  = gp[m0 * 8 + tid];
        sbe0[tid] = bep[m0 * 8 + tid];
    }
    if (tid < 16) swa[tid] = Wap[m0 * 16 + tid];
    if (tid < FA) {
        sba[tid]  = bap[m0 * 2 + tid];
        sga[tid]  = gap[m0 * 2 + tid];
        sbea[tid] = beap[m0 * 2 + tid];
    }
    __syncthreads();

    // column base: rows 4*tid..4*tid+3 (LDG.128)
    const float* xb = g_t0T + (ll)m0 * 64 * 2048 + 4 * tid;

    ull acc[RPT1][4];
    #pragma unroll
    for (int r = 0; r < RPT1; ++r)
        #pragma unroll
        for (int j = 0; j < 4; ++j) acc[r][j] = 0ull;

    #pragma unroll 1
    for (int c = 0; c < 16; ++c) {          // 16 groups of 4 dims
        float4 xq[4];
        #pragma unroll
        for (int d = 0; d < 4; ++d)
            xq[d] = *reinterpret_cast<const float4*>(xb + (ll)(c * 4 + d) * 2048);
        #pragma unroll
        for (int d = 0; d < 4; ++d) {
            ull w[4];
            #pragma unroll
            for (int p = 0; p < 4; ++p)
                w[p] = *reinterpret_cast<const ull*>(&sh_w[(c * 4 + d) * 8 + 2 * p]);
            const float* xf = reinterpret_cast<const float*>(&xq[d]);
            #pragma unroll
            for (int r = 0; r < RPT1; ++r) {
                ull xx = pack2(xf[r], xf[r]);
                #pragma unroll
                for (int j = 0; j < 4; ++j) acc[r][j] = fma2(xx, w[j], acc[r][j]);
            }
        }
    }

    float tv[RPT1][F];
    #pragma unroll
    for (int r = 0; r < RPT1; ++r)
        #pragma unroll
        for (int p = 0; p < 4; ++p) {
            float lo, hi; unpack2(acc[r][p], lo, hi);
            int P = 2 * p;
            tv[r][P]     = ftanh(lo + sb0[P]);
            tv[r][P + 1] = ftanh(hi + sb0[P + 1]);
        }

    #pragma unroll
    for (int f = 0; f < F; ++f) {
        float s = 0.f, ss = 0.f;
        #pragma unroll
        for (int r = 0; r < RPT1; ++r) { float v = tv[r][f]; s += v; ss += v * v; }
        #pragma unroll
        for (int o = 16; o; o >>= 1) {
            s  += __shfl_xor_sync(0xffffffffu, s, o);
            ss += __shfl_xor_sync(0xffffffffu, ss, o);
        }
        if (lane == 0) { red[f * NW1 + warp] = s; red[(F + f) * NW1 + warp] = ss; }
    }
    __syncthreads();
    if (tid < F) {
        int f = tid;
        float s = 0.f, ss = 0.f;
        #pragma unroll
        for (int w = 0; w < NW1; ++w) { s += red[f * NW1 + w]; ss += red[(F + f) * NW1 + w]; }
        float mu  = s  * (1.f / B_ROWS);
        float var = ss * (1.f / B_ROWS) - mu * mu;
        float a   = sg0[f] * rsqrtf(var + BN_EPS);
        stA[f] = a;
        stB[f] = sbe0[f] - mu * a;
    }
    __syncthreads();

    float av[RPT1][FA];
    #pragma unroll
    for (int r = 0; r < RPT1; ++r) {
        int b = 4 * tid + r;
        float tn[F];
        #pragma unroll
        for (int f = 0; f < F; ++f) tn[f] = fmaf(stA[f], tv[r][f], stB[f]);

        ll obase = ((ll)b * M + m0) * 8;
        #pragma unroll
        for (int q = 0; q < 2; ++q) {
            float4 v = make_float4(tn[q * 4], tn[q * 4 + 1], tn[q * 4 + 2], tn[q * 4 + 3]);
            *reinterpret_cast<float4*>(&out_t[obase + q * 4]) = v;
        }
        #pragma unroll
        for (int k = 0; k < 2; ++k) {
            float a = sba[k];
            #pragma unroll
            for (int h = 0; h < 8; ++h)
                a = fmaf(tn[h], swa[h * 2 + k], a);
            av[r][k] = ftanh(a);
        }
    }

    #pragma unroll
    for (int f = 0; f < FA; ++f) {
        float s = 0.f, ss = 0.f;
        #pragma unroll
        for (int r = 0; r < RPT1; ++r) { float v = av[r][f]; s += v; ss += v * v; }
        #pragma unroll
        for (int o = 16; o; o >>= 1) {
            s  += __shfl_xor_sync(0xffffffffu, s, o);
            ss += __shfl_xor_sync(0xffffffffu, ss, o);
        }
        if (lane == 0) { red[f * NW1 + warp] = s; red[(FA + f) * NW1 + warp] = ss; }
    }
    __syncthreads();
    if (tid < FA) {
        int f = tid;
        float s = 0.f, ss = 0.f;
        #pragma unroll
        for (int w = 0; w < NW1; ++w) { s += red[f * NW1 + w]; ss += red[(FA + f) * NW1 + w]; }
        float mu  = s  * (1.f / B_ROWS);
        float var = ss * (1.f / B_ROWS) - mu * mu;
        float a   = sga[f] * rsqrtf(var + BN_EPS);
        saA[f] = a;
        saB[f] = sbea[f] - mu * a;
    }
    __syncthreads();

    #pragma unroll
    for (int r = 0; r < RPT1; ++r) {
        int b = 4 * tid + r;
        ll obase = ((ll)b * M + m0) * 2;
        float2 v;
        v.x = fmaf(saA[0], av[r][0], saB[0]);
        v.y = fmaf(saA[1], av[r][1], saB[1]);
        *reinterpret_cast<float2*>(&out_a[obase]) = v;
    }
}

// Output layout: (aux0, aux1, t0, t1) flattened, fp32
static const ll OFF_A0 = 0;
static const ll OFF_A1 = 2048LL * 8192 * 2;            // 33,554,432
static const ll OFF_T0 = OFF_A1 + 2048LL * 1024 * 2;   // 37,748,736
static const ll OFF_T1 = OFF_T0 + 2048LL * 8192 * 8;   // 171,966,464

extern "C" void kernel_launch(void* const* d_in, const int* in_sizes, int n_in,
                              void* d_out, int out_size)
{
    const float* x    = (const float*)d_in[0];
    const float* W0   = (const float*)d_in[1];
    const float* b0   = (const float*)d_in[2];
    const float* g0   = (const float*)d_in[3];
    const float* be0  = (const float*)d_in[4];
    const float* Wa0  = (const float*)d_in[5];
    const float* ba0  = (const float*)d_in[6];
    const float* ga0  = (const float*)d_in[7];
    const float* bea0 = (const float*)d_in[8];
    const float* W1   = (const float*)d_in[9];
    const float* b1   = (const float*)d_in[10];
    const float* g1   = (const float*)d_in[11];
    const float* be1  = (const float*)d_in[12];
    const float* Wa1  = (const float*)d_in[13];
    const float* ba1  = (const float*)d_in[14];
    const float* ga1  = (const float*)d_in[15];
    const float* bea1 = (const float*)d_in[16];

    float* out  = (float*)d_out;
    float* aux0 = out + OFF_A0;
    float* aux1 = out + OFF_A1;
    float* t0   = out + OFF_T0;
    float* t1   = out + OFF_T1;

    // transpose x -> xT [64][2048]
    xT_kernel<<<dim3(2, 64), dim3(32, 8)>>>(x);

    // L0: 4096 blocks split into 3 launches (ncu skip-5-capture-1 lands on L0)
    const int s0 = (16 * B_ROWS + 1024 + 16 * NW0 * 2 + 2 * 16 + 2 * 4
                    + 3 * 16 + 32 + 3 * 4) * 4;   // ~139 KB
    cudaFuncSetAttribute(reinterpret_cast<const void*>(l0_kernel),
                         cudaFuncAttributeMaxDynamicSharedMemorySize, s0);
    l0_kernel<<<1365, T0, s0>>>(0,    W0, b0, g0, be0, Wa0, ba0, ga0, bea0, t0, aux0, 8192);
    l0_kernel<<<1365, T0, s0>>>(1365, W0, b0, g0, be0, Wa0, ba0, ga0, bea0, t0, aux0, 8192);
    l0_kernel<<<1366, T0, s0>>>(2730, W0, b0, g0, be0, Wa0, ba0, ga0, bea0, t0, aux0, 8192);

    // L1: 1024 roots; LDG.128 column reads from t0T
    l1_kernel<<<1024, T1>>>(
        W1, b1, g1, be1, Wa1, ba1, ga1, bea1, t1, aux1, 1024);
}

// round 17
// speedup vs baseline: 1.2006x; 1.2006x over previous
#include <cuda_runtime.h>

#define B_ROWS 2048
#define BN_EPS 1e-5f

typedef unsigned long long ull;
typedef long long ll;

// GMEM scratch: transposed operands (coalesced column access for both layers)
__device__ float g_xT[64 * 2048];                 // 512 KB, L2-resident
__device__ float g_t0T[65536ULL * 2048];          // 512 MB, normalized t0 transposed

__device__ __forceinline__ ull pack2(float lo, float hi) {
    ull r; asm("mov.b64 %0, {%1, %2};" : "=l"(r) : "f"(lo), "f"(hi)); return r;
}
__device__ __forceinline__ void unpack2(ull v, float& lo, float& hi) {
    asm("mov.b64 {%0, %1}, %2;" : "=f"(lo), "=f"(hi) : "l"(v));
}
__device__ __forceinline__ ull fma2(ull a, ull b, ull c) {
    ull d; asm("fma.rn.f32x2 %0, %1, %2, %3;" : "=l"(d) : "l"(a), "l"(b), "l"(c)); return d;
}
// accurate tanh (~1e-7 rel): MUFU.TANH at ~5e-4 is too close to the 1e-3 gate
__device__ __forceinline__ float ftanh(float x) {
    float e = __expf(2.0f * x);
    return 1.0f - __fdividef(2.0f, e + 1.0f);
}

// ============================ transpose x -> xT [64][2048] ============================
__global__ void xT_kernel(const float* __restrict__ x)
{
    __shared__ float t[32][33];
    int bx = blockIdx.x;          // d-tile (0..1)
    int by = blockIdx.y;          // row-tile (0..63)
    int lx = threadIdx.x, ly = threadIdx.y;   // 32 x 8
    #pragma unroll
    for (int k = 0; k < 4; ++k)
        t[ly + k * 8][lx] = x[(ll)(by * 32 + ly + k * 8) * 64 + bx * 32 + lx];
    __syncthreads();
    #pragma unroll
    for (int k = 0; k < 4; ++k)
        g_xT[(ll)(bx * 32 + ly + k * 8) * 2048 + by * 32 + lx] = t[lx][ly + k * 8];
}

// ============================ L0 kernel (R15 winner, single launch) ============================
#define T0 512
#define NW0 (T0 / 32)
#define RPT0 (B_ROWS / T0)   // 4

__device__ __forceinline__ void l0_fetch(float (&buf)[4][RPT0], int c, int tid) {
    #pragma unroll
    for (int d = 0; d < 4; ++d)
        #pragma unroll
        for (int r = 0; r < RPT0; ++r)
            buf[d][r] = g_xT[(ll)(c * 4 + d) * 2048 + tid + r * T0];
}

__device__ __forceinline__ void l0_compute(const float (&buf)[4][RPT0], int c,
                                           const ulonglong2* __restrict__ shw2,
                                           ull (&acc)[RPT0][8]) {
    #pragma unroll
    for (int d = 0; d < 4; ++d) {
        int k = c * 4 + d;
        #pragma unroll
        for (int g = 0; g < 2; ++g) {
            ulonglong2 w01 = shw2[(g * 64 + k) * 2];
            ulonglong2 w23 = shw2[(g * 64 + k) * 2 + 1];
            #pragma unroll
            for (int r = 0; r < RPT0; ++r) {
                ull xx = pack2(buf[d][r], buf[d][r]);
                acc[r][g * 4 + 0] = fma2(xx, w01.x, acc[r][g * 4 + 0]);
                acc[r][g * 4 + 1] = fma2(xx, w01.y, acc[r][g * 4 + 1]);
                acc[r][g * 4 + 2] = fma2(xx, w23.x, acc[r][g * 4 + 2]);
                acc[r][g * 4 + 3] = fma2(xx, w23.y, acc[r][g * 4 + 3]);
            }
        }
    }
}

__global__ void __launch_bounds__(T0, 1)
l0_kernel(const float* __restrict__ Wp,  const float* __restrict__ bp,
          const float* __restrict__ gp,  const float* __restrict__ bep,
          const float* __restrict__ Wap, const float* __restrict__ bap,
          const float* __restrict__ gap, const float* __restrict__ beap,
          float* __restrict__ out_t, float* __restrict__ out_a, int M)
{
    constexpr int F  = 16;
    constexpr int FA = 4;

    extern __shared__ float sm[];
    float* tile   = sm;                      // [16][2048] octet-rotated store tile
    float* sh_w   = sm + 16 * B_ROWS;        // [1024]
    float* red    = sh_w + 1024;             // [F*NW0*2]
    float* stA    = red + F * NW0 * 2;       // [16]
    float* stB    = stA + F;
    float* saA    = stB + F;                 // [4]
    float* saB    = saA + FA;
    float* sb0    = saB + FA;                // [16]
    float* sg0    = sb0 + F;
    float* sbe0   = sg0 + F;
    float* swa    = sbe0 + F;                // [32]
    float* sba    = swa + 32;                // [4]
    float* sga    = sba + FA;
    float* sbea   = sga + FA;

    const int tid  = threadIdx.x;
    const int lane = tid & 31;
    const int warp = tid >> 5;
    const int m0   = blockIdx.x * 2;

    // ---- params to smem ----
    for (int i = tid; i < 1024; i += T0) sh_w[i] = Wp[(ll)m0 * 512 + i];
    if (tid < F) {
        sb0[tid]  = bp[m0 * 8 + tid];
        sg0[tid]  = gp[m0 * 8 + tid];
        sbe0[tid] = bep[m0 * 8 + tid];
    }
    if (tid < 32) swa[tid] = Wap[m0 * 16 + tid];
    if (tid < FA) {
        sba[tid]  = bap[m0 * 2 + tid];
        sga[tid]  = gap[m0 * 2 + tid];
        sbea[tid] = beap[m0 * 2 + tid];
    }
    __syncthreads();

    // ---- Phase 1: GEMM (64 -> 16), double-buffered register prefetch of x ----
    ull acc[RPT0][8];
    #pragma unroll
    for (int r = 0; r < RPT0; ++r)
        #pragma unroll
        for (int j = 0; j < 8; ++j) acc[r][j] = 0ull;

    const ulonglong2* shw2 = reinterpret_cast<const ulonglong2*>(sh_w);

    float xA[4][RPT0], xB[4][RPT0];
    l0_fetch(xA, 0, tid);                    // preload chunk 0

    #pragma unroll 1
    for (int cc = 0; cc < 8; ++cc) {
        int c0 = 2 * cc, c1 = 2 * cc + 1;
        l0_fetch(xB, c1, tid);               // prefetch c1 while computing c0
        l0_compute(xA, c0, shw2, acc);
        if (cc < 7) l0_fetch(xA, c1 + 1, tid);
        l0_compute(xB, c1, shw2, acc);
    }

    // ---- Phase 2: bias + tanh ----
    float tv[RPT0][F];
    #pragma unroll
    for (int r = 0; r < RPT0; ++r)
        #pragma unroll
        for (int g = 0; g < 2; ++g)
            #pragma unroll
            for (int p = 0; p < 4; ++p) {
                float lo, hi; unpack2(acc[r][g * 4 + p], lo, hi);
                int P = g * 8 + 2 * p;
                tv[r][P]     = ftanh(lo + sb0[P]);
                tv[r][P + 1] = ftanh(hi + sb0[P + 1]);
            }

    // ---- batch stats ----
    #pragma unroll
    for (int f = 0; f < F; ++f) {
        float s = 0.f, ss = 0.f;
        #pragma unroll
        for (int r = 0; r < RPT0; ++r) { float v = tv[r][f]; s += v; ss += v * v; }
        #pragma unroll
        for (int o = 16; o; o >>= 1) {
            s  += __shfl_xor_sync(0xffffffffu, s, o);
            ss += __shfl_xor_sync(0xffffffffu, ss, o);
        }
        if (lane == 0) { red[f * NW0 + warp] = s; red[(F + f) * NW0 + warp] = ss; }
    }
    __syncthreads();
    if (tid < F) {
        int f = tid;
        float s = 0.f, ss = 0.f;
        #pragma unroll
        for (int w = 0; w < NW0; ++w) { s += red[f * NW0 + w]; ss += red[(F + f) * NW0 + w]; }
        float mu  = s  * (1.f / B_ROWS);
        float var = ss * (1.f / B_ROWS) - mu * mu;
        float a   = sg0[f] * rsqrtf(var + BN_EPS);
        stA[f] = a;
        stB[f] = sbe0[f] - mu * a;
    }
    __syncthreads();

    // ---- Phase 3: normalize -> t0T direct (coalesced STG.32) + tile -> out_t; aux fused ----
    float av[RPT0][FA];
    #pragma unroll
    for (int q = 0; q < RPT0; ++q) {
        int row = tid + q * T0;
        int rb32 = row & ~31;
        float tn[F];
        #pragma unroll
        for (int f = 0; f < F; ++f) tn[f] = fmaf(stA[f], tv[q][f], stB[f]);

        // transposed scratch for L1: lanes = consecutive rows -> coalesced
        #pragma unroll
        for (int f = 0; f < F; ++f)
            g_t0T[(ll)(m0 * 8 + f) * 2048 + row] = tn[f];

        // octet-rotated tile for the output-layout store
        #pragma unroll
        for (int f = 0; f < F; ++f)
            tile[f * B_ROWS + rb32 + ((row + 8 * (f >> 2)) & 31)] = tn[f];

        #pragma unroll
        for (int g = 0; g < 2; ++g)
            #pragma unroll
            for (int k = 0; k < 2; ++k) {
                float a = sba[g * 2 + k];
                #pragma unroll
                for (int h = 0; h < 8; ++h)
                    a = fmaf(tn[g * 8 + h], swa[(g * 8 + h) * 2 + k], a);
                av[q][g * 2 + k] = ftanh(a);
            }
    }
    __syncthreads();

    // cooperative output-layout store: 2048 rows x 4 parts = 8192 items
    #pragma unroll
    for (int ii = 0; ii < 16; ++ii) {
        int j   = tid + ii * T0;
        int row = j >> 2;
        int p   = j & 3;
        int rb  = (row & ~31) + ((row + 8 * p) & 31);
        float4 v;
        v.x = tile[(p * 4 + 0) * B_ROWS + rb];
        v.y = tile[(p * 4 + 1) * B_ROWS + rb];
        v.z = tile[(p * 4 + 2) * B_ROWS + rb];
        v.w = tile[(p * 4 + 3) * B_ROWS + rb];
        *reinterpret_cast<float4*>(&out_t[(ll)row * M * 8 + m0 * 8 + p * 4]) = v;
    }

    // ---- Phase 4: aux stats + store ----
    #pragma unroll
    for (int f = 0; f < FA; ++f) {
        float s = 0.f, ss = 0.f;
        #pragma unroll
        for (int r = 0; r < RPT0; ++r) { float v = av[r][f]; s += v; ss += v * v; }
        #pragma unroll
        for (int o = 16; o; o >>= 1) {
            s  += __shfl_xor_sync(0xffffffffu, s, o);
            ss += __shfl_xor_sync(0xffffffffu, ss, o);
        }
        if (lane == 0) { red[f * NW0 + warp] = s; red[(FA + f) * NW0 + warp] = ss; }
    }
    __syncthreads();
    if (tid < FA) {
        int f = tid;
        float s = 0.f, ss = 0.f;
        #pragma unroll
        for (int w = 0; w < NW0; ++w) { s += red[f * NW0 + w]; ss += red[(FA + f) * NW0 + w]; }
        float mu  = s  * (1.f / B_ROWS);
        float var = ss * (1.f / B_ROWS) - mu * mu;
        float a   = sga[f] * rsqrtf(var + BN_EPS);
        saA[f] = a;
        saB[f] = sbea[f] - mu * a;
    }
    __syncthreads();

    #pragma unroll
    for (int r = 0; r < RPT0; ++r) {
        int b = tid + r * T0;
        ll obase = ((ll)b * M + m0) * 2;
        float4 v;
        v.x = fmaf(saA[0], av[r][0], saB[0]);
        v.y = fmaf(saA[1], av[r][1], saB[1]);
        v.z = fmaf(saA[2], av[r][2], saB[2]);
        v.w = fmaf(saA[3], av[r][3], saB[3]);
        *reinterpret_cast<float4*>(&out_a[obase]) = v;
    }
}

// ============================ L1 kernel (R14 verbatim — ~135us) ============================
#define T1 512
#define NW1 (T1 / 32)
#define RPT1 (B_ROWS / T1)   // 4

__global__ void __launch_bounds__(T1, 1)
l1_kernel(const float* __restrict__ Wp,  const float* __restrict__ bp,
          const float* __restrict__ gp,  const float* __restrict__ bep,
          const float* __restrict__ Wap, const float* __restrict__ bap,
          const float* __restrict__ gap, const float* __restrict__ beap,
          float* __restrict__ out_t, float* __restrict__ out_a, int M)
{
    constexpr int F = 8, FA = 2;

    __shared__ float sh_w[512];
    __shared__ float sb0[F], sg0[F], sbe0[F];
    __shared__ float swa[16];
    __shared__ float sba[FA], sga[FA], sbea[FA];
    __shared__ float red[F * NW1 * 2];
    __shared__ float stA[F], stB[F];
    __shared__ float saA[FA], saB[FA];

    const int tid  = threadIdx.x;
    const int lane = tid & 31;
    const int warp = tid >> 5;
    const int m0   = blockIdx.x;

    for (int i = tid; i < 512; i += T1) sh_w[i] = Wp[(ll)m0 * 512 + i];
    if (tid < F) {
        sb0[tid]  = bp[m0 * 8 + tid];
        sg0[tid]  = gp[m0 * 8 + tid];
        sbe0[tid] = bep[m0 * 8 + tid];
    }
    if (tid < 16) swa[tid] = Wap[m0 * 16 + tid];
    if (tid < FA) {
        sba[tid]  = bap[m0 * 2 + tid];
        sga[tid]  = gap[m0 * 2 + tid];
        sbea[tid] = beap[m0 * 2 + tid];
    }
    __syncthreads();

    // column base: rows 4*tid..4*tid+3 (LDG.128)
    const float* xb = g_t0T + (ll)m0 * 64 * 2048 + 4 * tid;

    ull acc[RPT1][4];
    #pragma unroll
    for (int r = 0; r < RPT1; ++r)
        #pragma unroll
        for (int j = 0; j < 4; ++j) acc[r][j] = 0ull;

    #pragma unroll 1
    for (int c = 0; c < 16; ++c) {          // 16 groups of 4 dims
        float4 xq[4];
        #pragma unroll
        for (int d = 0; d < 4; ++d)
            xq[d] = *reinterpret_cast<const float4*>(xb + (ll)(c * 4 + d) * 2048);
        #pragma unroll
        for (int d = 0; d < 4; ++d) {
            ull w[4];
            #pragma unroll
            for (int p = 0; p < 4; ++p)
                w[p] = *reinterpret_cast<const ull*>(&sh_w[(c * 4 + d) * 8 + 2 * p]);
            const float* xf = reinterpret_cast<const float*>(&xq[d]);
            #pragma unroll
            for (int r = 0; r < RPT1; ++r) {
                ull xx = pack2(xf[r], xf[r]);
                #pragma unroll
                for (int j = 0; j < 4; ++j) acc[r][j] = fma2(xx, w[j], acc[r][j]);
            }
        }
    }

    float tv[RPT1][F];
    #pragma unroll
    for (int r = 0; r < RPT1; ++r)
        #pragma unroll
        for (int p = 0; p < 4; ++p) {
            float lo, hi; unpack2(acc[r][p], lo, hi);
            int P = 2 * p;
            tv[r][P]     = ftanh(lo + sb0[P]);
            tv[r][P + 1] = ftanh(hi + sb0[P + 1]);
        }

    #pragma unroll
    for (int f = 0; f < F; ++f) {
        float s = 0.f, ss = 0.f;
        #pragma unroll
        for (int r = 0; r < RPT1; ++r) { float v = tv[r][f]; s += v; ss += v * v; }
        #pragma unroll
        for (int o = 16; o; o >>= 1) {
            s  += __shfl_xor_sync(0xffffffffu, s, o);
            ss += __shfl_xor_sync(0xffffffffu, ss, o);
        }
        if (lane == 0) { red[f * NW1 + warp] = s; red[(F + f) * NW1 + warp] = ss; }
    }
    __syncthreads();
    if (tid < F) {
        int f = tid;
        float s = 0.f, ss = 0.f;
        #pragma unroll
        for (int w = 0; w < NW1; ++w) { s += red[f * NW1 + w]; ss += red[(F + f) * NW1 + w]; }
        float mu  = s  * (1.f / B_ROWS);
        float var = ss * (1.f / B_ROWS) - mu * mu;
        float a   = sg0[f] * rsqrtf(var + BN_EPS);
        stA[f] = a;
        stB[f] = sbe0[f] - mu * a;
    }
    __syncthreads();

    float av[RPT1][FA];
    #pragma unroll
    for (int r = 0; r < RPT1; ++r) {
        int b = 4 * tid + r;
        float tn[F];
        #pragma unroll
        for (int f = 0; f < F; ++f) tn[f] = fmaf(stA[f], tv[r][f], stB[f]);

        ll obase = ((ll)b * M + m0) * 8;
        #pragma unroll
        for (int q = 0; q < 2; ++q) {
            float4 v = make_float4(tn[q * 4], tn[q * 4 + 1], tn[q * 4 + 2], tn[q * 4 + 3]);
            *reinterpret_cast<float4*>(&out_t[obase + q * 4]) = v;
        }
        #pragma unroll
        for (int k = 0; k < 2; ++k) {
            float a = sba[k];
            #pragma unroll
            for (int h = 0; h < 8; ++h)
                a = fmaf(tn[h], swa[h * 2 + k], a);
            av[r][k] = ftanh(a);
        }
    }

    #pragma unroll
    for (int f = 0; f < FA; ++f) {
        float s = 0.f, ss = 0.f;
        #pragma unroll
        for (int r = 0; r < RPT1; ++r) { float v = av[r][f]; s += v; ss += v * v; }
        #pragma unroll
        for (int o = 16; o; o >>= 1) {
            s  += __shfl_xor_sync(0xffffffffu, s, o);
            ss += __shfl_xor_sync(0xffffffffu, ss, o);
        }
        if (lane == 0) { red[f * NW1 + warp] = s; red[(FA + f) * NW1 + warp] = ss; }
    }
    __syncthreads();
    if (tid < FA) {
        int f = tid;
        float s = 0.f, ss = 0.f;
        #pragma unroll
        for (int w = 0; w < NW1; ++w) { s += red[f * NW1 + w]; ss += red[(FA + f) * NW1 + w]; }
        float mu  = s  * (1.f / B_ROWS);
        float var = ss * (1.f / B_ROWS) - mu * mu;
        float a   = sga[f] * rsqrtf(var + BN_EPS);
        saA[f] = a;
        saB[f] = sbea[f] - mu * a;
    }
    __syncthreads();

    #pragma unroll
    for (int r = 0; r < RPT1; ++r) {
        int b = 4 * tid + r;
        ll obase = ((ll)b * M + m0) * 2;
        float2 v;
        v.x = fmaf(saA[0], av[r][0], saB[0]);
        v.y = fmaf(saA[1], av[r][1], saB[1]);
        *reinterpret_cast<float2*>(&out_a[obase]) = v;
    }
}

// Output layout: (aux0, aux1, t0, t1) flattened, fp32
static const ll OFF_A0 = 0;
static const ll OFF_A1 = 2048LL * 8192 * 2;            // 33,554,432
static const ll OFF_T0 = OFF_A1 + 2048LL * 1024 * 2;   // 37,748,736
static const ll OFF_T1 = OFF_T0 + 2048LL * 8192 * 8;   // 171,966,464

extern "C" void kernel_launch(void* const* d_in, const int* in_sizes, int n_in,
                              void* d_out, int out_size)
{
    const float* x    = (const float*)d_in[0];
    const float* W0   = (const float*)d_in[1];
    const float* b0   = (const float*)d_in[2];
    const float* g0   = (const float*)d_in[3];
    const float* be0  = (const float*)d_in[4];
    const float* Wa0  = (const float*)d_in[5];
    const float* ba0  = (const float*)d_in[6];
    const float* ga0  = (const float*)d_in[7];
    const float* bea0 = (const float*)d_in[8];
    const float* W1   = (const float*)d_in[9];
    const float* b1   = (const float*)d_in[10];
    const float* g1   = (const float*)d_in[11];
    const float* be1  = (const float*)d_in[12];
    const float* Wa1  = (const float*)d_in[13];
    const float* ba1  = (const float*)d_in[14];
    const float* ga1  = (const float*)d_in[15];
    const float* bea1 = (const float*)d_in[16];

    float* out  = (float*)d_out;
    float* aux0 = out + OFF_A0;
    float* aux1 = out + OFF_A1;
    float* t0   = out + OFF_T0;
    float* t1   = out + OFF_T1;

    // transpose x -> xT [64][2048]
    xT_kernel<<<dim3(2, 64), dim3(32, 8)>>>(x);

    // L0: ONE launch of 4096 blocks (3-way profiling split cost ~2 extra
    // wave-times ≈ 50us in tail quantization — removed)
    const int s0 = (16 * B_ROWS + 1024 + 16 * NW0 * 2 + 2 * 16 + 2 * 4
                    + 3 * 16 + 32 + 3 * 4) * 4;   // ~136 KB
    cudaFuncSetAttribute(reinterpret_cast<const void*>(l0_kernel),
                         cudaFuncAttributeMaxDynamicSharedMemorySize, s0);
    l0_kernel<<<4096, T0, s0>>>(
        W0, b0, g0, be0, Wa0, ba0, ga0, bea0, t0, aux0, 8192);

    // L1: 1024 roots; LDG.128 column reads from t0T
    l1_kernel<<<1024, T1>>>(
        W1, b1, g1, be1, Wa1, ba1, ga1, bea1, t1, aux1, 1024);
}